// round 14
// baseline (speedup 1.0000x reference)
#include <cuda_runtime.h>

// Sinkhorn: 65536 matrices of 36x36, 21 iterations of row/col log-normalization,
// temperature 0.01, output exp(log_alpha).
//
// Base-2 potential form: matrix = y - U_i - V_j, y = input * (100*log2 e).
//   row pass: U_i = lse2_j(y_ij - V_j);  col pass: V_j = lse2_i(y_ij - U_i)
// start V=0; after 21 (row,col) pairs, out = 2^(y - U - V).
//
// R11 = R9 skeleton, max phase eliminated for iters >= 3: the lse is shifted
// by the thread's PREVIOUS potential (lse is shift-invariant while the sum
// stays in (2^-100, 2^100); window check + exact-max fallback guarantees
// correctness). Iters 0-2 (large transient drift) use exact max. No t[36],
// no yreg: only 4 accumulators live -> ~45 regs -> 4 blocks/SM (36 warps).
// STRIDE=40 makes rows 16B-aligned (LDS.128 row loads); columns stay
// bank-conflict-free (bank = (l + 8i) mod 32, all 32 distinct per phase).

#define NMAT_PER_BLOCK 8
#define THREADS 288            // 8 groups * 36 = 9 full warps
#define NDIM 36
#define STRIDE 40              // float4-aligned rows; conflict-free columns
#define MAT_SMEM (NDIM * STRIDE)   // 1440 floats
#define MAT_ELEMS (NDIM * NDIM)    // 1296
#define SCALE 144.269504088896340736f   // 100 * log2(e)
#define NITERS 21
#define WIN_LO 7.8886e-31f     // 2^-100
#define WIN_HI 1.2677e+30f     // 2^100

__device__ __forceinline__ float ex2f(float x) {
    float y; asm("ex2.approx.ftz.f32 %0, %1;" : "=f"(y) : "f"(x)); return y;
}
__device__ __forceinline__ float lg2f(float x) {
    float y; asm("lg2.approx.ftz.f32 %0, %1;" : "=f"(y) : "f"(x)); return y;
}
__device__ __forceinline__ bool in_window(float s) {
    return (s > WIN_LO) && (s < WIN_HI);   // false for 0, inf, NaN, negative
}

__global__ __launch_bounds__(THREADS, 4)
void sinkhorn_kernel(const float* __restrict__ in, float* __restrict__ out)
{
    __shared__ __align__(16) float sy[NMAT_PER_BLOCK * MAT_SMEM];
    __shared__ __align__(16) float sU[NMAT_PER_BLOCK * NDIM];
    __shared__ __align__(16) float sV[NMAT_PER_BLOCK * NDIM];

    const int tid = threadIdx.x;
    const long long base = (long long)blockIdx.x * (NMAT_PER_BLOCK * MAT_ELEMS);

    // ---- load: coalesced float4 from global, scatter into padded smem, fused scale
    {
        const float4* in4 = (const float4*)(in + base);
        for (int k = tid; k < (NMAT_PER_BLOCK * MAT_ELEMS) / 4; k += THREADS) {
            float4 v = in4[k];
            float vals[4] = {v.x, v.y, v.z, v.w};
            int e = k * 4;
            #pragma unroll
            for (int q = 0; q < 4; q++) {
                int idx = e + q;
                int g   = idx / MAT_ELEMS;
                int rem = idx - g * MAT_ELEMS;
                int r   = rem / NDIM;
                int c   = rem - r * NDIM;
                sy[g * MAT_SMEM + r * STRIDE + c] = vals[q] * SCALE;
            }
        }
    }
    sV[tid] = 0.0f;                       // 288 == THREADS
    __syncthreads();

    const int g = tid / NDIM;          // which matrix in this block
    const int l = tid - g * NDIM;      // row (row pass) / col (col pass) index

    const float4* U4 = (const float4*)&sU[g * NDIM];
    const float4* V4 = (const float4*)&sV[g * NDIM];
    float* U = &sU[g * NDIM];
    float* V = &sV[g * NDIM];
    const float4* row4 = (const float4*)&sy[g * MAT_SMEM + l * STRIDE]; // 160B-aligned
    const float*  scol = &sy[g * MAT_SMEM + l];

    // ---- pass helpers (no arrays: exp consumes its arg immediately) ----
    auto row_sum = [&](float m) -> float {
        float s0 = 0.f, s1 = 0.f, s2 = 0.f, s3 = 0.f;
        #pragma unroll
        for (int q = 0; q < 9; q++) {
            float4 y = row4[q];
            float4 v = V4[q];
            s0 += ex2f((y.x - m) - v.x);
            s1 += ex2f((y.y - m) - v.y);
            s2 += ex2f((y.z - m) - v.z);
            s3 += ex2f((y.w - m) - v.w);
        }
        return (s0 + s1) + (s2 + s3);
    };
    auto row_max = [&]() -> float {
        float m0 = -3e38f, m1 = -3e38f, m2 = -3e38f, m3 = -3e38f;
        #pragma unroll
        for (int q = 0; q < 9; q++) {
            float4 y = row4[q];
            float4 v = V4[q];
            m0 = fmaxf(m0, y.x - v.x);  m1 = fmaxf(m1, y.y - v.y);
            m2 = fmaxf(m2, y.z - v.z);  m3 = fmaxf(m3, y.w - v.w);
        }
        return fmaxf(fmaxf(m0, m1), fmaxf(m2, m3));
    };
    auto col_sum = [&](float m) -> float {
        float s0 = 0.f, s1 = 0.f, s2 = 0.f, s3 = 0.f;
        #pragma unroll
        for (int q = 0; q < 9; q++) {
            float4 u = U4[q];
            s0 += ex2f((scol[(4*q+0) * STRIDE] - m) - u.x);
            s1 += ex2f((scol[(4*q+1) * STRIDE] - m) - u.y);
            s2 += ex2f((scol[(4*q+2) * STRIDE] - m) - u.z);
            s3 += ex2f((scol[(4*q+3) * STRIDE] - m) - u.w);
        }
        return (s0 + s1) + (s2 + s3);
    };
    auto col_max = [&]() -> float {
        float m0 = -3e38f, m1 = -3e38f, m2 = -3e38f, m3 = -3e38f;
        #pragma unroll
        for (int q = 0; q < 9; q++) {
            float4 u = U4[q];
            m0 = fmaxf(m0, scol[(4*q+0) * STRIDE] - u.x);
            m1 = fmaxf(m1, scol[(4*q+1) * STRIDE] - u.y);
            m2 = fmaxf(m2, scol[(4*q+2) * STRIDE] - u.z);
            m3 = fmaxf(m3, scol[(4*q+3) * STRIDE] - u.w);
        }
        return fmaxf(fmaxf(m0, m1), fmaxf(m2, m3));
    };

    float uown = 0.0f, vown = 0.0f;

    #pragma unroll 1
    for (int it = 0; it < NITERS; it++) {
        // ---- row pass: U[l] = m + log2(sum_j 2^(y[l][j] - V[j] - m))
        {
            float m = uown, s = 0.0f;
            bool exact = (it < 3);
            if (!exact) {
                s = row_sum(m);
                exact = !in_window(s);
            }
            if (exact) {          // transient iters + rare fallback
                m = row_max();
                s = row_sum(m);
            }
            uown = m + lg2f(s);
            U[l] = uown;
        }
        __syncthreads();

        // ---- col pass: V[l] = m + log2(sum_i 2^(y[i][l] - U[i] - m))
        {
            float m = vown, s = 0.0f;
            bool exact = (it < 3);
            if (!exact) {
                s = col_sum(m);
                exact = !in_window(s);
            }
            if (exact) {
                m = col_max();
                s = col_sum(m);
            }
            vown = m + lg2f(s);
            V[l] = vown;
        }
        __syncthreads();
    }

    // ---- output: overwrite my row of sy with 2^(y - U - V) (float4 in/out)
    {
        const float u = uown;
        float4* od4 = (float4*)&sy[g * MAT_SMEM + l * STRIDE];
        #pragma unroll
        for (int q = 0; q < 9; q++) {
            float4 y = od4[q];
            float4 v = V4[q];
            od4[q] = make_float4(ex2f((y.x - u) - v.x),
                                 ex2f((y.y - u) - v.y),
                                 ex2f((y.z - u) - v.z),
                                 ex2f((y.w - u) - v.w));
        }
    }
    __syncthreads();
    {
        float4* out4 = (float4*)(out + base);
        for (int k = tid; k < (NMAT_PER_BLOCK * MAT_ELEMS) / 4; k += THREADS) {
            int e = k * 4;
            float r[4];
            #pragma unroll
            for (int q = 0; q < 4; q++) {
                int idx = e + q;
                int gg  = idx / MAT_ELEMS;
                int rem = idx - gg * MAT_ELEMS;
                int rr  = rem / NDIM;
                int cc  = rem - rr * NDIM;
                r[q] = sy[gg * MAT_SMEM + rr * STRIDE + cc];
            }
            out4[k] = make_float4(r[0], r[1], r[2], r[3]);
        }
    }
}

extern "C" void kernel_launch(void* const* d_in, const int* in_sizes, int n_in,
                              void* d_out, int out_size) {
    const float* in = (const float*)d_in[0];
    float* out = (float*)d_out;
    int num_mats = in_sizes[0] / MAT_ELEMS;          // 65536
    int grid = num_mats / NMAT_PER_BLOCK;            // 8192
    sinkhorn_kernel<<<grid, THREADS>>>(in, out);
}

// round 15
// speedup vs baseline: 2.0547x; 2.0547x over previous
#include <cuda_runtime.h>

// Sinkhorn: 65536 matrices of 36x36, 21 iterations of row/col log-normalization,
// temperature 0.01, output exp(log_alpha).
//
// Base-2 potential form: matrix = y - U_i - V_j, y = input * (100*log2 e).
//   row pass: U_i = lse2_j(y_ij - V_j);  col pass: V_j = lse2_i(y_ij - U_i)
// start V=0; after 21 (row,col) pairs, out = 2^(y - U - V).
//
// R15 = R9 (the 1018us baseline: dense, branch-free, exact max every pass,
// pure MUFU exp, smem-fed t[36], 3 blocks/SM) + ONE change: STRIDE 37->40 so
// every row is 16B-aligned -> row-pass and output-pass smem traffic becomes
// float4 (9x LDS.128 instead of 36x LDS.32), shrinking the inter-barrier
// region (~218 -> ~185 issue slots/pass) and with it the barrier drain.
// Columns at stride 40 have at most a 2-way conflict on 4 lane-pairs in
// group-boundary warps; LSU is far from the binding pipe (MUFU at ~86%).

#define NMAT_PER_BLOCK 8
#define THREADS 288            // 8 groups * 36 = 9 full warps
#define NDIM 36
#define STRIDE 40              // float4-aligned rows (group base 1440 = 0 mod 32)
#define MAT_SMEM (NDIM * STRIDE)   // 1440 floats
#define MAT_ELEMS (NDIM * NDIM)    // 1296
#define SCALE 144.269504088896340736f   // 100 * log2(e)
#define NITERS 21

__device__ __forceinline__ float ex2f(float x) {
    float y; asm("ex2.approx.ftz.f32 %0, %1;" : "=f"(y) : "f"(x)); return y;
}
__device__ __forceinline__ float lg2f(float x) {
    float y; asm("lg2.approx.ftz.f32 %0, %1;" : "=f"(y) : "f"(x)); return y;
}

__global__ __launch_bounds__(THREADS, 3)
void sinkhorn_kernel(const float* __restrict__ in, float* __restrict__ out)
{
    __shared__ __align__(16) float sy[NMAT_PER_BLOCK * MAT_SMEM];
    __shared__ __align__(16) float sU[NMAT_PER_BLOCK * NDIM];
    __shared__ __align__(16) float sV[NMAT_PER_BLOCK * NDIM];

    const int tid = threadIdx.x;
    const long long base = (long long)blockIdx.x * (NMAT_PER_BLOCK * MAT_ELEMS);

    // ---- load: coalesced float4 from global, scatter into padded smem, fused scale
    {
        const float4* in4 = (const float4*)(in + base);
        for (int k = tid; k < (NMAT_PER_BLOCK * MAT_ELEMS) / 4; k += THREADS) {
            float4 v = in4[k];
            float vals[4] = {v.x, v.y, v.z, v.w};
            int e = k * 4;
            #pragma unroll
            for (int q = 0; q < 4; q++) {
                int idx = e + q;
                int g   = idx / MAT_ELEMS;
                int rem = idx - g * MAT_ELEMS;
                int r   = rem / NDIM;
                int c   = rem - r * NDIM;
                sy[g * MAT_SMEM + r * STRIDE + c] = vals[q] * SCALE;
            }
        }
    }
    sV[tid] = 0.0f;                       // 288 == THREADS
    __syncthreads();

    const int g = tid / NDIM;          // which matrix in this block
    const int l = tid - g * NDIM;      // row (row pass) / col (col pass) index

    const float4* U4 = (const float4*)&sU[g * NDIM];
    const float4* V4 = (const float4*)&sV[g * NDIM];
    float* U = &sU[g * NDIM];
    float* V = &sV[g * NDIM];
    const float4* row4 = (const float4*)&sy[g * MAT_SMEM + l * STRIDE];  // 16B-aligned
    const float*  scol = &sy[g * MAT_SMEM + l];

    #pragma unroll 1
    for (int it = 0; it < NITERS; it++) {
        // ---- row pass: U[l] = m + log2(sum_j 2^(y[l][j] - V[j] - m))
        {
            float t[NDIM];
            float m0 = -1e30f, m1 = -1e30f, m2 = -1e30f, m3 = -1e30f;
            #pragma unroll
            for (int q = 0; q < 9; q++) {
                float4 y = row4[q];               // LDS.128
                float4 v = V4[q];                 // LDS.128 broadcast
                t[4*q+0] = y.x - v.x;
                t[4*q+1] = y.y - v.y;
                t[4*q+2] = y.z - v.z;
                t[4*q+3] = y.w - v.w;
                m0 = fmaxf(m0, t[4*q+0]);  m1 = fmaxf(m1, t[4*q+1]);
                m2 = fmaxf(m2, t[4*q+2]);  m3 = fmaxf(m3, t[4*q+3]);
            }
            float m = fmaxf(fmaxf(m0, m1), fmaxf(m2, m3));
            float s0 = 0.f, s1 = 0.f, s2 = 0.f, s3 = 0.f;
            #pragma unroll
            for (int j = 0; j < NDIM; j += 4) {
                s0 += ex2f(t[j]   - m);
                s1 += ex2f(t[j+1] - m);
                s2 += ex2f(t[j+2] - m);
                s3 += ex2f(t[j+3] - m);
            }
            U[l] = m + lg2f((s0 + s1) + (s2 + s3));
        }
        __syncthreads();

        // ---- col pass: V[l] = m + log2(sum_i 2^(y[i][l] - U[i] - m))
        {
            float t[NDIM];
            float m0 = -1e30f, m1 = -1e30f, m2 = -1e30f, m3 = -1e30f;
            #pragma unroll
            for (int q = 0; q < 9; q++) {
                float4 u = U4[q];                 // broadcast
                t[4*q+0] = scol[(4*q+0) * STRIDE] - u.x;
                t[4*q+1] = scol[(4*q+1) * STRIDE] - u.y;
                t[4*q+2] = scol[(4*q+2) * STRIDE] - u.z;
                t[4*q+3] = scol[(4*q+3) * STRIDE] - u.w;
                m0 = fmaxf(m0, t[4*q+0]);  m1 = fmaxf(m1, t[4*q+1]);
                m2 = fmaxf(m2, t[4*q+2]);  m3 = fmaxf(m3, t[4*q+3]);
            }
            float m = fmaxf(fmaxf(m0, m1), fmaxf(m2, m3));
            float s0 = 0.f, s1 = 0.f, s2 = 0.f, s3 = 0.f;
            #pragma unroll
            for (int i = 0; i < NDIM; i += 4) {
                s0 += ex2f(t[i]   - m);
                s1 += ex2f(t[i+1] - m);
                s2 += ex2f(t[i+2] - m);
                s3 += ex2f(t[i+3] - m);
            }
            V[l] = m + lg2f((s0 + s1) + (s2 + s3));
        }
        __syncthreads();
    }

    // ---- output: overwrite my row of sy with 2^(y - U - V), float4 in/out
    {
        const float u = U[l];
        float4* od4 = (float4*)&sy[g * MAT_SMEM + l * STRIDE];
        #pragma unroll
        for (int q = 0; q < 9; q++) {
            float4 y = od4[q];
            float4 v = V4[q];
            od4[q] = make_float4(ex2f((y.x - u) - v.x),
                                 ex2f((y.y - u) - v.y),
                                 ex2f((y.z - u) - v.z),
                                 ex2f((y.w - u) - v.w));
        }
    }
    __syncthreads();
    {
        float4* out4 = (float4*)(out + base);
        for (int k = tid; k < (NMAT_PER_BLOCK * MAT_ELEMS) / 4; k += THREADS) {
            int e = k * 4;
            float r[4];
            #pragma unroll
            for (int q = 0; q < 4; q++) {
                int idx = e + q;
                int gg  = idx / MAT_ELEMS;
                int rem = idx - gg * MAT_ELEMS;
                int rr  = rem / NDIM;
                int cc  = rem - rr * NDIM;
                r[q] = sy[gg * MAT_SMEM + rr * STRIDE + cc];
            }
            out4[k] = make_float4(r[0], r[1], r[2], r[3]);
        }
    }
}

extern "C" void kernel_launch(void* const* d_in, const int* in_sizes, int n_in,
                              void* d_out, int out_size) {
    const float* in = (const float*)d_in[0];
    float* out = (float*)d_out;
    int num_mats = in_sizes[0] / MAT_ELEMS;          // 65536
    int grid = num_mats / NMAT_PER_BLOCK;            // 8192
    sinkhorn_kernel<<<grid, THREADS>>>(in, out);
}